// round 1
// baseline (speedup 1.0000x reference)
#include <cuda_runtime.h>
#include <math.h>

#define NTOT 4096
#define DIM  256
#define KC   32
#define INV_TEMP (1.0f/0.07f)

// ---------------- scratch (device globals; no allocations) ----------------
__device__ float g_sim[(size_t)NTOT * NTOT];       // 64 MB: sim = A@B^T / TEMP
__device__ float g_rowmax[NTOT];
__device__ float g_rowsum[NTOT];
__device__ int   g_rowarg[NTOT];
__device__ float g_cpm[16 * NTOT];                 // column partial max (16 row-splits)
__device__ float g_cps[16 * NTOT];                 // column partial sumexp
__device__ float g_colmax[NTOT];
__device__ float g_colsum[NTOT];
__device__ int   g_hard[NTOT];
__device__ float g_terms[4 * NTOT];                // rowterm, colterm, triplet, acc

// ---------------- packed f32x2 helpers (Blackwell FFMA2) ----------------
__device__ __forceinline__ unsigned long long pack2(float lo, float hi) {
    unsigned long long r;
    asm("mov.b64 %0, {%1, %2};" : "=l"(r) : "f"(lo), "f"(hi));
    return r;
}
__device__ __forceinline__ void fma2(unsigned long long &c, unsigned long long a,
                                     unsigned long long b) {
    asm("fma.rn.f32x2 %0, %1, %2, %3;" : "=l"(c) : "l"(a), "l"(b), "l"(c));
}
__device__ __forceinline__ float2 unpack2(unsigned long long v) {
    float2 f;
    asm("mov.b64 {%0, %1}, %2;" : "=f"(f.x), "=f"(f.y) : "l"(v));
    return f;
}

// ---------------- GEMM: g_sim = (A @ B^T) * INV_TEMP ----------------
// 128x128 C-tile per block, 256 threads, 8x8 micro-tile, K-chunks of 32.
__global__ __launch_bounds__(256, 2) void gemm_sim(const float* __restrict__ A,
                                                   const float* __restrict__ B) {
    __shared__ float As[KC][132];   // As[k][row], pad to 132 for alignment
    __shared__ float Bs[KC][132];   // Bs[k][col]
    const int tid = threadIdx.x;
    const int tx = tid & 15, ty = tid >> 4;
    const int rowBase = blockIdx.y * 128;
    const int colBase = blockIdx.x * 128;
    const float* Ab = A + (size_t)rowBase * DIM;
    const float* Bb = B + (size_t)colBase * DIM;

    unsigned long long acc[8][4];
#pragma unroll
    for (int i = 0; i < 8; i++)
#pragma unroll
        for (int j = 0; j < 4; j++) acc[i][j] = 0ULL;   // bits of (0.f, 0.f)

    for (int k0 = 0; k0 < DIM; k0 += KC) {
        // load A/B chunks (128 rows x 32 k) transposed into smem
#pragma unroll
        for (int i = 0; i < 4; i++) {
            int f = tid + i * 256;      // float4 index: 1024 per operand
            int r = f >> 3, q = f & 7;  // row, k-quad
            float4 va = *(const float4*)(Ab + (size_t)r * DIM + k0 + q * 4);
            As[q * 4 + 0][r] = va.x; As[q * 4 + 1][r] = va.y;
            As[q * 4 + 2][r] = va.z; As[q * 4 + 3][r] = va.w;
            float4 vb = *(const float4*)(Bb + (size_t)r * DIM + k0 + q * 4);
            Bs[q * 4 + 0][r] = vb.x; Bs[q * 4 + 1][r] = vb.y;
            Bs[q * 4 + 2][r] = vb.z; Bs[q * 4 + 3][r] = vb.w;
        }
        __syncthreads();
#pragma unroll
        for (int k = 0; k < KC; k++) {
            float4 a0 = *(const float4*)&As[k][ty * 8];
            float4 a1 = *(const float4*)&As[k][ty * 8 + 4];
            float4 b0 = *(const float4*)&Bs[k][tx * 8];
            float4 b1 = *(const float4*)&Bs[k][tx * 8 + 4];
            unsigned long long bp[4] = { pack2(b0.x, b0.y), pack2(b0.z, b0.w),
                                         pack2(b1.x, b1.y), pack2(b1.z, b1.w) };
            float av[8] = { a0.x, a0.y, a0.z, a0.w, a1.x, a1.y, a1.z, a1.w };
#pragma unroll
            for (int i = 0; i < 8; i++) {
                unsigned long long ap = pack2(av[i], av[i]);
#pragma unroll
                for (int j = 0; j < 4; j++) fma2(acc[i][j], ap, bp[j]);
            }
        }
        __syncthreads();
    }
    // epilogue: scale and store
#pragma unroll
    for (int i = 0; i < 8; i++) {
        int row = rowBase + ty * 8 + i;
        float* out = g_sim + (size_t)row * NTOT + colBase + tx * 8;
        float2 c0 = unpack2(acc[i][0]), c1 = unpack2(acc[i][1]);
        float2 c2 = unpack2(acc[i][2]), c3 = unpack2(acc[i][3]);
        float4 w0 = make_float4(c0.x * INV_TEMP, c0.y * INV_TEMP,
                                c1.x * INV_TEMP, c1.y * INV_TEMP);
        float4 w1 = make_float4(c2.x * INV_TEMP, c2.y * INV_TEMP,
                                c3.x * INV_TEMP, c3.y * INV_TEMP);
        *(float4*)out = w0;
        *(float4*)(out + 4) = w1;
    }
}

// ---------------- row stats: max, argmax (first), sumexp ----------------
__global__ void row_stats() {
    const int row = blockIdx.x;
    const float* r = g_sim + (size_t)row * NTOT;
    const int tid = threadIdx.x;
    __shared__ float sv[256];
    __shared__ int   si[256];
    float m = -3.4e38f; int mi = 0;
    for (int j = tid; j < NTOT; j += 256) {
        float v = r[j];
        if (v > m) { m = v; mi = j; }
    }
    sv[tid] = m; si[tid] = mi;
    __syncthreads();
    for (int s = 128; s > 0; s >>= 1) {
        if (tid < s) {
            float v2 = sv[tid + s]; int i2 = si[tid + s];
            if (v2 > sv[tid] || (v2 == sv[tid] && i2 < si[tid])) { sv[tid] = v2; si[tid] = i2; }
        }
        __syncthreads();
    }
    m = sv[0];
    int argi = si[0];
    float ssum = 0.f;
    for (int j = tid; j < NTOT; j += 256) ssum += __expf(r[j] - m);
    __syncthreads();
    sv[tid] = ssum;
    __syncthreads();
    for (int s = 128; s > 0; s >>= 1) {
        if (tid < s) sv[tid] += sv[tid + s];
        __syncthreads();
    }
    if (tid == 0) { g_rowmax[row] = m; g_rowsum[row] = sv[0]; g_rowarg[row] = argi; }
}

// ---------------- column stats: online softmax partials over 256-row splits ----
__global__ void col_part() {
    int col = blockIdx.x * 256 + threadIdx.x;
    int r0  = blockIdx.y * 256;
    float m = -3.4e38f, s = 0.f;
    const float* p = g_sim + (size_t)r0 * NTOT + col;
    for (int r = 0; r < 256; r++) {
        float v = p[(size_t)r * NTOT];
        if (v > m) { s = s * __expf(m - v) + 1.0f; m = v; }
        else       { s += __expf(v - m); }
    }
    g_cpm[blockIdx.y * NTOT + col] = m;
    g_cps[blockIdx.y * NTOT + col] = s;
}

__global__ void col_merge() {
    int col = blockIdx.x * 256 + threadIdx.x;
    float m = -3.4e38f, s = 0.f;
    for (int p = 0; p < 16; p++) {
        float mp = g_cpm[p * NTOT + col], sp = g_cps[p * NTOT + col];
        if (mp > m) { s = s * __expf(m - mp) + sp; m = mp; }
        else        { s += sp * __expf(mp - m); }
    }
    g_colmax[col] = m;
    g_colsum[col] = s;
}

// ---------------- hard-negative mining on diagonal 128x128 blocks ----------
__global__ void hard_mine() {
    int b = blockIdx.x, k = threadIdx.x;
    const float* base = g_sim + (size_t)(b * 128 + k) * NTOT + b * 128;
    float m = -3.4e38f; int mi = 0;
    for (int j = 0; j < 128; j++) {
        if (j == k) continue;
        float v = base[j];
        if (v > m) { m = v; mi = j; }
    }
    g_hard[b * 128 + k] = b * 128 + mi;
}

// ---------------- per-row terms: one warp per row ----------------
__global__ void terms_kernel(const float* __restrict__ A, const float* __restrict__ B) {
    int warp = (blockIdx.x * blockDim.x + threadIdx.x) >> 5;
    int lane = threadIdx.x & 31;
    if (warp >= NTOT) return;
    int i = warp;
    const float* a  = A + (size_t)i * DIM;
    const float* bp = B + (size_t)i * DIM;
    const float* bn = B + (size_t)g_hard[i] * DIM;
    float ps = 0.f, ns = 0.f;
    for (int t = lane; t < DIM; t += 32) {
        float av = a[t];
        float d1 = av - bp[t] + 1e-6f; ps += d1 * d1;
        float d2 = av - bn[t] + 1e-6f; ns += d2 * d2;
    }
#pragma unroll
    for (int o = 16; o > 0; o >>= 1) {
        ps += __shfl_xor_sync(0xffffffff, ps, o);
        ns += __shfl_xor_sync(0xffffffff, ns, o);
    }
    if (lane == 0) {
        float trip = sqrtf(ps) - sqrtf(ns) + 0.5f;
        if (trip < 0.f) trip = 0.f;
        float d = g_sim[(size_t)i * NTOT + i];
        g_terms[i]            = g_rowmax[i] + logf(g_rowsum[i]) - d;   // -logp_A2B[i,i]
        g_terms[NTOT + i]     = g_colmax[i] + logf(g_colsum[i]) - d;   // -logp_B2A[i,i]
        g_terms[2 * NTOT + i] = trip;
        g_terms[3 * NTOT + i] = (g_rowarg[i] == i) ? 1.0f : 0.0f;
    }
}

// ---------------- final deterministic reduction ----------------
__global__ void final_reduce(float* __restrict__ out) {
    __shared__ float sm[256];
    int tid = threadIdx.x;
    float sums[4];
    for (int c = 0; c < 4; c++) {
        float s = 0.f;
        for (int j = tid; j < NTOT; j += 256) s += g_terms[c * NTOT + j];
        sm[tid] = s;
        __syncthreads();
        for (int st = 128; st > 0; st >>= 1) {
            if (tid < st) sm[tid] += sm[tid + st];
            __syncthreads();
        }
        sums[c] = sm[0];
        __syncthreads();
    }
    if (tid == 0) {
        float info = 0.5f * (sums[0] + sums[1]) / (float)NTOT;
        float trip = sums[2] / (float)NTOT;
        float acc  = sums[3] / (float)NTOT;
        out[0] = info + 0.1f * trip;   // total_loss
        out[1] = info;                 // info_nce_loss
        out[2] = trip;                 // triplet_loss
        out[3] = acc;                  // acc
    }
}

extern "C" void kernel_launch(void* const* d_in, const int* in_sizes, int n_in,
                              void* d_out, int out_size) {
    const float* A = (const float*)d_in[0];   // embeddings_A [32,128,256]
    const float* B = (const float*)d_in[1];   // embeddings_B [32,128,256]
    float* out = (float*)d_out;

    gemm_sim<<<dim3(32, 32), 256>>>(A, B);
    row_stats<<<NTOT, 256>>>();
    col_part<<<dim3(16, 16), 256>>>();
    col_merge<<<16, 256>>>();
    hard_mine<<<32, 128>>>();
    terms_kernel<<<512, 256>>>(A, B);
    final_reduce<<<1, 256>>>(out);
}

// round 3
// speedup vs baseline: 2.1210x; 2.1210x over previous
#include <cuda_runtime.h>
#include <cuda_bf16.h>
#include <math.h>
#include <stdint.h>

#define NTOT 4096
#define DIM  256
#define KEXT 768
#define INV_TEMP (1.0f/0.07f)
#define NEG_INF -3.4e38f

// ---------------- scratch (device globals; no allocations) ----------------
__device__ __nv_bfloat16 g_Ae[(size_t)NTOT * KEXT];   // [Ahi | Ahi | Alo]
__device__ __nv_bfloat16 g_Be[(size_t)NTOT * KEXT];   // [Bhi | Blo | Bhi]
__device__ float g_rpm[32 * NTOT];   // row partial max   (p = col-tile)
__device__ float g_rps[32 * NTOT];   // row partial sumexp
__device__ int   g_rpa[32 * NTOT];   // row partial argmax (global col)
__device__ float g_cpm[32 * NTOT];   // col partial max   (p = row-tile)
__device__ float g_cps[32 * NTOT];
__device__ float g_diag[NTOT];
__device__ int   g_hard[NTOT];
__device__ float g_terms[4 * NTOT];

// ---------------- helpers ----------------
__device__ __forceinline__ uint32_t smem_u32(const void* p) {
    uint32_t a;
    asm("{ .reg .u64 t; cvta.to.shared.u64 t, %1; cvt.u32.u64 %0, t; }" : "=r"(a) : "l"(p));
    return a;
}
__device__ __forceinline__ void hilo(float x, unsigned short &h, unsigned short &l) {
    __nv_bfloat16 bh = __float2bfloat16(x);
    __nv_bfloat16 bl = __float2bfloat16(x - __bfloat162float(bh));
    h = *reinterpret_cast<unsigned short*>(&bh);
    l = *reinterpret_cast<unsigned short*>(&bl);
}
#define LDMX4(r0, r1, r2, r3, addr) \
    asm volatile("ldmatrix.sync.aligned.m8n8.x4.shared.b16 {%0,%1,%2,%3}, [%4];" \
        : "=r"(r0), "=r"(r1), "=r"(r2), "=r"(r3) : "r"(addr))

#define MMA_BF16(c, a, b) \
    asm volatile("mma.sync.aligned.m16n8k16.row.col.f32.bf16.bf16.f32 " \
        "{%0,%1,%2,%3}, {%4,%5,%6,%7}, {%8,%9}, {%0,%1,%2,%3};" \
        : "+f"((c)[0]), "+f"((c)[1]), "+f"((c)[2]), "+f"((c)[3]) \
        : "r"((a)[0]), "r"((a)[1]), "r"((a)[2]), "r"((a)[3]), "r"((b)[0]), "r"((b)[1]))

// ---------------- split: fp32 -> extended bf16 operands ----------------
__global__ void split_ext(const float* __restrict__ A, const float* __restrict__ B) {
    int i = blockIdx.x * blockDim.x + threadIdx.x;   // float4 index, 262144 total
    int row = i >> 6;
    int c0  = (i & 63) << 2;
    float4 va = ((const float4*)A)[i];
    float4 vb = ((const float4*)B)[i];
    ushort4 ah, al, bh, bl;
    hilo(va.x, ah.x, al.x); hilo(va.y, ah.y, al.y);
    hilo(va.z, ah.z, al.z); hilo(va.w, ah.w, al.w);
    hilo(vb.x, bh.x, bl.x); hilo(vb.y, bh.y, bl.y);
    hilo(vb.z, bh.z, bl.z); hilo(vb.w, bl.w = bl.w, bl.w);   // placeholder overwritten below
    hilo(vb.w, bh.w, bl.w);
    size_t ra = (size_t)row * KEXT;
    *(ushort4*)(g_Ae + ra + c0)       = ah;
    *(ushort4*)(g_Ae + ra + 256 + c0) = ah;
    *(ushort4*)(g_Ae + ra + 512 + c0) = al;
    *(ushort4*)(g_Be + ra + c0)       = bh;
    *(ushort4*)(g_Be + ra + 256 + c0) = bl;
    *(ushort4*)(g_Be + ra + 512 + c0) = bh;
}

// ---------------- fused GEMM + tile reductions ----------------
// 128x128 tile, 256 threads (8 warps: 2 M x 4 N), K=768 in 24 chunks of 32.
// SMEM: two operand stages (A 10240B + B 10240B each), then reused as 128x129 f32 tile.
#define ROWB 80u            // bytes per smem operand row (32 bf16 + pad)
#define STG_SZ 20480u
#define CT_STRIDE 129
#define SMEM_GEMM (128 * CT_STRIDE * 4)   // 66048 >= 2*STG_SZ

__global__ __launch_bounds__(256, 2) void gemm_fused() {
    extern __shared__ char smem[];
    const uint32_t sb = smem_u32(smem);
    const int tid = threadIdx.x;
    const int lid = tid & 31;
    const int wid = tid >> 5;
    const int warpM = wid >> 2;          // 0..1
    const int warpN = wid & 3;           // 0..3
    const int rowBase = blockIdx.y * 128;
    const int colBase = blockIdx.x * 128;

    const __nv_bfloat16* ga = g_Ae + (size_t)rowBase * KEXT;
    const __nv_bfloat16* gb = g_Be + (size_t)colBase * KEXT;

    float c[4][4][4];
#pragma unroll
    for (int mf = 0; mf < 4; mf++)
#pragma unroll
        for (int nf = 0; nf < 4; nf++)
#pragma unroll
            for (int r = 0; r < 4; r++) c[mf][nf][r] = 0.f;

    auto load_chunk = [&](int kk, int s) {
        uint32_t aB = sb + s * STG_SZ;
        uint32_t bB = aB + 10240u;
#pragma unroll
        for (int i = 0; i < 2; i++) {
            int cc = tid + i * 256;            // 0..511 16B-chunks
            int r = cc >> 2, q = cc & 3;
            const void* sa = ga + (size_t)r * KEXT + kk * 32 + q * 8;
            asm volatile("cp.async.cg.shared.global [%0], [%1], 16;"
                         :: "r"(aB + r * ROWB + q * 16), "l"(sa));
            const void* sbp = gb + (size_t)r * KEXT + kk * 32 + q * 8;
            asm volatile("cp.async.cg.shared.global [%0], [%1], 16;"
                         :: "r"(bB + r * ROWB + q * 16), "l"(sbp));
        }
        asm volatile("cp.async.commit_group;");
    };

    load_chunk(0, 0);
    load_chunk(1, 1);

    for (int kk = 0; kk < 24; kk++) {
        const int s = kk & 1;
        if (kk < 23) asm volatile("cp.async.wait_group 1;");
        else         asm volatile("cp.async.wait_group 0;");
        __syncthreads();

        const uint32_t aOff = sb + s * STG_SZ;
        const uint32_t bOff = aOff + 10240u;
#pragma unroll
        for (int k2 = 0; k2 < 2; k2++) {
            uint32_t a[4][4];
            const int arow = warpM * 64 + (lid & 15);
            const uint32_t akb = (uint32_t)(k2 * 32 + (lid >> 4) * 16);
#pragma unroll
            for (int mf = 0; mf < 4; mf++)
                LDMX4(a[mf][0], a[mf][1], a[mf][2], a[mf][3],
                      aOff + (uint32_t)(arow + mf * 16) * ROWB + akb);
            uint32_t b[4][2];
            const int nrow = warpN * 32 + ((lid >> 4) << 3) + (lid & 7);
            const uint32_t bkb = (uint32_t)(k2 * 32 + (((lid >> 3) & 1) << 4));
#pragma unroll
            for (int bp = 0; bp < 2; bp++) {
                uint32_t r0, r1, r2, r3;
                LDMX4(r0, r1, r2, r3, bOff + (uint32_t)(nrow + bp * 16) * ROWB + bkb);
                b[2 * bp][0] = r0;     b[2 * bp][1] = r1;
                b[2 * bp + 1][0] = r2; b[2 * bp + 1][1] = r3;
            }
#pragma unroll
            for (int mf = 0; mf < 4; mf++)
#pragma unroll
                for (int nf = 0; nf < 4; nf++)
                    MMA_BF16(c[mf][nf], a[mf], b[nf]);
        }
        __syncthreads();
        if (kk + 2 < 24) load_chunk(kk + 2, s);
    }

    // ---- write scaled tile to SMEM (reuse operand space) ----
    float* Ct = (float*)smem;
#pragma unroll
    for (int mf = 0; mf < 4; mf++) {
        const int row = warpM * 64 + mf * 16 + (lid >> 2);
#pragma unroll
        for (int nf = 0; nf < 4; nf++) {
            const int col = warpN * 32 + nf * 8 + (lid & 3) * 2;
            Ct[row * CT_STRIDE + col]           = c[mf][nf][0] * INV_TEMP;
            Ct[row * CT_STRIDE + col + 1]       = c[mf][nf][1] * INV_TEMP;
            Ct[(row + 8) * CT_STRIDE + col]     = c[mf][nf][2] * INV_TEMP;
            Ct[(row + 8) * CT_STRIDE + col + 1] = c[mf][nf][3] * INV_TEMP;
        }
    }
    __syncthreads();

    // ---- tile reductions ----
    const bool diag = (blockIdx.x == blockIdx.y);
    if (tid < 128) {
        const int r = tid;
        const float* rp = Ct + r * CT_STRIDE;
        float m = NEG_INF; int arg = 0;
        for (int j = 0; j < 128; j++) {
            float v = rp[j];
            if (v > m) { m = v; arg = j; }
        }
        float s = 0.f;
        for (int j = 0; j < 128; j++) s += __expf(rp[j] - m);
        const int rowg = rowBase + r;
        g_rpm[blockIdx.x * NTOT + rowg] = m;
        g_rps[blockIdx.x * NTOT + rowg] = s;
        g_rpa[blockIdx.x * NTOT + rowg] = colBase + arg;
        if (diag) {
            float hm = NEG_INF; int ha = 0;
            for (int j = 0; j < 128; j++) {
                if (j == r) continue;
                float v = rp[j];
                if (v > hm) { hm = v; ha = j; }
            }
            g_hard[rowg] = colBase + ha;
            g_diag[rowg] = rp[r];
        }
    } else {
        const int cidx = tid - 128;
        float m = NEG_INF;
        for (int r = 0; r < 128; r++) {
            float v = Ct[r * CT_STRIDE + cidx];
            if (v > m) m = v;
        }
        float s = 0.f;
        for (int r = 0; r < 128; r++) s += __expf(Ct[r * CT_STRIDE + cidx] - m);
        const int colg = colBase + cidx;
        g_cpm[blockIdx.y * NTOT + colg] = m;
        g_cps[blockIdx.y * NTOT + colg] = s;
    }
}

// ---------------- merge row partials -> rowterm + acc ----------------
__global__ void row_merge() {
    int i = blockIdx.x * 256 + threadIdx.x;
    float m = NEG_INF; int arg = 0;
    for (int p = 0; p < 32; p++) {
        float mp = g_rpm[p * NTOT + i];
        if (mp > m) { m = mp; arg = g_rpa[p * NTOT + i]; }
    }
    float s = 0.f;
    for (int p = 0; p < 32; p++)
        s += g_rps[p * NTOT + i] * __expf(g_rpm[p * NTOT + i] - m);
    g_terms[i]            = m + logf(s) - g_diag[i];
    g_terms[3 * NTOT + i] = (arg == i) ? 1.0f : 0.0f;
}

// ---------------- merge col partials -> colterm ----------------
__global__ void col_merge() {
    int i = blockIdx.x * 256 + threadIdx.x;
    float m = NEG_INF;
    for (int p = 0; p < 32; p++) {
        float mp = g_cpm[p * NTOT + i];
        if (mp > m) m = mp;
    }
    float s = 0.f;
    for (int p = 0; p < 32; p++)
        s += g_cps[p * NTOT + i] * __expf(g_cpm[p * NTOT + i] - m);
    g_terms[NTOT + i] = m + logf(s) - g_diag[i];
}

// ---------------- triplet terms: one warp per row ----------------
__global__ void triplet_kernel(const float* __restrict__ A, const float* __restrict__ B) {
    int warp = (blockIdx.x * blockDim.x + threadIdx.x) >> 5;
    int lane = threadIdx.x & 31;
    if (warp >= NTOT) return;
    int i = warp;
    const float* a  = A + (size_t)i * DIM;
    const float* bp = B + (size_t)i * DIM;
    const float* bn = B + (size_t)g_hard[i] * DIM;
    float ps = 0.f, ns = 0.f;
    for (int t = lane; t < DIM; t += 32) {
        float av = a[t];
        float d1 = av - bp[t] + 1e-6f; ps += d1 * d1;
        float d2 = av - bn[t] + 1e-6f; ns += d2 * d2;
    }
#pragma unroll
    for (int o = 16; o > 0; o >>= 1) {
        ps += __shfl_xor_sync(0xffffffff, ps, o);
        ns += __shfl_xor_sync(0xffffffff, ns, o);
    }
    if (lane == 0) {
        float trip = sqrtf(ps) - sqrtf(ns) + 0.5f;
        if (trip < 0.f) trip = 0.f;
        g_terms[2 * NTOT + i] = trip;
    }
}

// ---------------- final deterministic reduction ----------------
__global__ void final_reduce(float* __restrict__ out) {
    __shared__ float sm[256];
    int tid = threadIdx.x;
    float sums[4];
    for (int cc = 0; cc < 4; cc++) {
        float s = 0.f;
        for (int j = tid; j < NTOT; j += 256) s += g_terms[cc * NTOT + j];
        sm[tid] = s;
        __syncthreads();
        for (int st = 128; st > 0; st >>= 1) {
            if (tid < st) sm[tid] += sm[tid + st];
            __syncthreads();
        }
        sums[cc] = sm[0];
        __syncthreads();
    }
    if (tid == 0) {
        float info = 0.5f * (sums[0] + sums[1]) / (float)NTOT;
        float trip = sums[2] / (float)NTOT;
        float acc  = sums[3] / (float)NTOT;
        out[0] = info + 0.1f * trip;
        out[1] = info;
        out[2] = trip;
        out[3] = acc;
    }
}

extern "C" void kernel_launch(void* const* d_in, const int* in_sizes, int n_in,
                              void* d_out, int out_size) {
    const float* A = (const float*)d_in[0];
    const float* B = (const float*)d_in[1];
    float* out = (float*)d_out;

    static bool configured = false;
    if (!configured) {
        cudaFuncSetAttribute(gemm_fused, cudaFuncAttributeMaxDynamicSharedMemorySize,
                             SMEM_GEMM);
        configured = true;
    }

    split_ext<<<1024, 256>>>(A, B);
    gemm_fused<<<dim3(32, 32), 256, SMEM_GEMM>>>();
    row_merge<<<16, 256>>>();
    col_merge<<<16, 256>>>();
    triplet_kernel<<<512, 256>>>(A, B);
    final_reduce<<<1, 256>>>(out);
}

// round 4
// speedup vs baseline: 3.1910x; 1.5045x over previous
#include <cuda_runtime.h>
#include <cuda_fp16.h>
#include <math.h>
#include <stdint.h>

#define NTOT 4096
#define DIM  256
#define INV_TEMP (1.0f/0.07f)
#define NEG_INF -3.4e38f

// ---------------- scratch (device globals; no allocations) ----------------
__device__ __half g_Ah[(size_t)NTOT * DIM];   // A * INV_TEMP, fp16
__device__ __half g_Bh[(size_t)NTOT * DIM];   // B, fp16
__device__ float g_rpm[32 * NTOT];   // row partial max   (p = col-tile)
__device__ float g_rps[32 * NTOT];   // row partial sumexp
__device__ int   g_rpa[32 * NTOT];   // row partial argmax (global col)
__device__ float g_cpm[32 * NTOT];   // col partial max   (p = row-tile)
__device__ float g_cps[32 * NTOT];
__device__ float g_diag[NTOT];       // logit-scale diag
__device__ int   g_hard[NTOT];
__device__ float g_terms[4 * NTOT];

// ---------------- helpers ----------------
__device__ __forceinline__ uint32_t smem_u32(const void* p) {
    uint32_t a;
    asm("{ .reg .u64 t; cvta.to.shared.u64 t, %1; cvt.u32.u64 %0, t; }" : "=r"(a) : "l"(p));
    return a;
}
#define LDMX4(r0, r1, r2, r3, addr) \
    asm volatile("ldmatrix.sync.aligned.m8n8.x4.shared.b16 {%0,%1,%2,%3}, [%4];" \
        : "=r"(r0), "=r"(r1), "=r"(r2), "=r"(r3) : "r"(addr))

#define MMA_F16(c, a, b) \
    asm volatile("mma.sync.aligned.m16n8k16.row.col.f32.f16.f16.f32 " \
        "{%0,%1,%2,%3}, {%4,%5,%6,%7}, {%8,%9}, {%0,%1,%2,%3};" \
        : "+f"((c)[0]), "+f"((c)[1]), "+f"((c)[2]), "+f"((c)[3]) \
        : "r"((a)[0]), "r"((a)[1]), "r"((a)[2]), "r"((a)[3]), "r"((b)[0]), "r"((b)[1]))

// ---------------- split: fp32 -> fp16 (A prescaled by 1/TEMP) ----------------
__global__ void split_f16(const float* __restrict__ A, const float* __restrict__ B) {
    int i = blockIdx.x * blockDim.x + threadIdx.x;   // 0..131071, 8 floats each
    float4 a0 = ((const float4*)A)[2 * i];
    float4 a1 = ((const float4*)A)[2 * i + 1];
    float4 b0 = ((const float4*)B)[2 * i];
    float4 b1 = ((const float4*)B)[2 * i + 1];
    __half ha[8] = { __float2half_rn(a0.x * INV_TEMP), __float2half_rn(a0.y * INV_TEMP),
                     __float2half_rn(a0.z * INV_TEMP), __float2half_rn(a0.w * INV_TEMP),
                     __float2half_rn(a1.x * INV_TEMP), __float2half_rn(a1.y * INV_TEMP),
                     __float2half_rn(a1.z * INV_TEMP), __float2half_rn(a1.w * INV_TEMP) };
    __half hb[8] = { __float2half_rn(b0.x), __float2half_rn(b0.y),
                     __float2half_rn(b0.z), __float2half_rn(b0.w),
                     __float2half_rn(b1.x), __float2half_rn(b1.y),
                     __float2half_rn(b1.z), __float2half_rn(b1.w) };
    *(uint4*)(g_Ah + (size_t)i * 8) = *(uint4*)ha;
    *(uint4*)(g_Bh + (size_t)i * 8) = *(uint4*)hb;
}

// ---------------- fused GEMM + tile reductions ----------------
// 128x128 logit tile per CTA, 256 threads (2x4 warps), K=256 in 4 chunks of 64.
// SMEM: 2 operand stages (A 18432B + B 18432B each = 36864/stage), reused as Ct 128x128 f32.
#define ROWB 144u                       // 64 fp16 = 128B + 16B pad
#define OP_SZ (128u * ROWB)             // 18432
#define STG_SZ (2u * OP_SZ)             // 36864
#define SMEM_GEMM (2 * STG_SZ)          // 73728 (>= Ct 65536)

__global__ __launch_bounds__(256, 2) void gemm_fused() {
    extern __shared__ char smem[];
    const uint32_t sb = smem_u32(smem);
    const int tid = threadIdx.x;
    const int lid = tid & 31;
    const int wid = tid >> 5;
    const int warpM = wid >> 2;          // 0..1
    const int warpN = wid & 3;           // 0..3
    const int rowBase = blockIdx.y * 128;
    const int colBase = blockIdx.x * 128;

    const __half* ga = g_Ah + (size_t)rowBase * DIM;
    const __half* gb = g_Bh + (size_t)colBase * DIM;

    float c[4][4][4];
#pragma unroll
    for (int mf = 0; mf < 4; mf++)
#pragma unroll
        for (int nf = 0; nf < 4; nf++)
#pragma unroll
            for (int r = 0; r < 4; r++) c[mf][nf][r] = 0.f;

    // chunk kk: 64 k-values; 128 rows x 8 16B-chunks per operand = 1024 chunks
    auto load_chunk = [&](int kk, int s) {
        uint32_t aB = sb + s * STG_SZ;
        uint32_t bB = aB + OP_SZ;
#pragma unroll
        for (int i = 0; i < 4; i++) {
            int cc = tid + i * 256;           // 0..1023
            int r = cc >> 3, q = cc & 7;
            const void* sa = ga + (size_t)r * DIM + kk * 64 + q * 8;
            asm volatile("cp.async.cg.shared.global [%0], [%1], 16;"
                         :: "r"(aB + r * ROWB + q * 16), "l"(sa));
            const void* sbp = gb + (size_t)r * DIM + kk * 64 + q * 8;
            asm volatile("cp.async.cg.shared.global [%0], [%1], 16;"
                         :: "r"(bB + r * ROWB + q * 16), "l"(sbp));
        }
        asm volatile("cp.async.commit_group;");
    };

    load_chunk(0, 0);
    load_chunk(1, 1);

#pragma unroll
    for (int kk = 0; kk < 4; kk++) {
        const int s = kk & 1;
        if (kk < 3) asm volatile("cp.async.wait_group 1;");
        else        asm volatile("cp.async.wait_group 0;");
        __syncthreads();

        const uint32_t aOff = sb + s * STG_SZ;
        const uint32_t bOff = aOff + OP_SZ;
#pragma unroll
        for (int k2 = 0; k2 < 4; k2++) {
            uint32_t a[4][4];
            const int arow = warpM * 64 + (lid & 15);
            const uint32_t akb = (uint32_t)(k2 * 32 + (lid >> 4) * 16);
#pragma unroll
            for (int mf = 0; mf < 4; mf++)
                LDMX4(a[mf][0], a[mf][1], a[mf][2], a[mf][3],
                      aOff + (uint32_t)(arow + mf * 16) * ROWB + akb);
            uint32_t b[4][2];
            const int nrow = warpN * 32 + ((lid >> 4) << 3) + (lid & 7);
            const uint32_t bkb = (uint32_t)(k2 * 32 + (((lid >> 3) & 1) << 4));
#pragma unroll
            for (int bp = 0; bp < 2; bp++) {
                uint32_t r0, r1, r2, r3;
                LDMX4(r0, r1, r2, r3, bOff + (uint32_t)(nrow + bp * 16) * ROWB + bkb);
                b[2 * bp][0] = r0;     b[2 * bp][1] = r1;
                b[2 * bp + 1][0] = r2; b[2 * bp + 1][1] = r3;
            }
#pragma unroll
            for (int mf = 0; mf < 4; mf++)
#pragma unroll
                for (int nf = 0; nf < 4; nf++)
                    MMA_F16(c[mf][nf], a[mf], b[nf]);
        }
        __syncthreads();
        if (kk + 2 < 4) load_chunk(kk + 2, s);
    }

    // ---- write logit tile to SMEM (reuse operand space; stride 128 floats) ----
    float* Ct = (float*)smem;
#pragma unroll
    for (int mf = 0; mf < 4; mf++) {
        const int row = warpM * 64 + mf * 16 + (lid >> 2);
#pragma unroll
        for (int nf = 0; nf < 4; nf++) {
            const int col = warpN * 32 + nf * 8 + (lid & 3) * 2;
            Ct[row * 128 + col]           = c[mf][nf][0];
            Ct[row * 128 + col + 1]       = c[mf][nf][1];
            Ct[(row + 8) * 128 + col]     = c[mf][nf][2];
            Ct[(row + 8) * 128 + col + 1] = c[mf][nf][3];
        }
    }
    __syncthreads();

    // ---- tile reductions ----
    const bool diag = (blockIdx.x == blockIdx.y);
    if (tid < 128) {
        const int r = tid;
        const float* rp = Ct + r * 128;
        float m = NEG_INF; int arg = 0;
#pragma unroll 8
        for (int j4 = 0; j4 < 32; j4++) {
            float4 v = ((const float4*)rp)[j4];
            if (v.x > m) { m = v.x; arg = j4 * 4; }
            if (v.y > m) { m = v.y; arg = j4 * 4 + 1; }
            if (v.z > m) { m = v.z; arg = j4 * 4 + 2; }
            if (v.w > m) { m = v.w; arg = j4 * 4 + 3; }
        }
        float s = 0.f;
#pragma unroll 8
        for (int j4 = 0; j4 < 32; j4++) {
            float4 v = ((const float4*)rp)[j4];
            s += __expf(v.x - m) + __expf(v.y - m) + __expf(v.z - m) + __expf(v.w - m);
        }
        const int rowg = rowBase + r;
        g_rpm[blockIdx.x * NTOT + rowg] = m;
        g_rps[blockIdx.x * NTOT + rowg] = s;
        g_rpa[blockIdx.x * NTOT + rowg] = colBase + arg;
        if (diag) {
            float hm = NEG_INF; int ha = 0;
            for (int j = 0; j < 128; j++) {
                if (j == r) continue;
                float v = rp[j];
                if (v > hm) { hm = v; ha = j; }
            }
            g_hard[rowg] = colBase + ha;
            g_diag[rowg] = rp[r];
        }
    } else {
        const int cidx = tid - 128;
        float m = NEG_INF;
        for (int r = 0; r < 128; r++) {
            float v = Ct[r * 128 + cidx];
            if (v > m) m = v;
        }
        float s = 0.f;
        for (int r = 0; r < 128; r++) s += __expf(Ct[r * 128 + cidx] - m);
        const int colg = colBase + cidx;
        g_cpm[blockIdx.y * NTOT + colg] = m;
        g_cps[blockIdx.y * NTOT + colg] = s;
    }
}

// ---------------- fused merge (row + col + triplet): one warp per row ----------------
__global__ void merge_all(const float* __restrict__ A, const float* __restrict__ B) {
    const int i = blockIdx.x * 8 + (threadIdx.x >> 5);
    const int lane = threadIdx.x & 31;

    // row partials: lane = tile p
    float m0 = g_rpm[lane * NTOT + i];
    float s0 = g_rps[lane * NTOT + i];
    int   a0 = g_rpa[lane * NTOT + i];
    float bm = m0; int bp = lane; int ba = a0;
#pragma unroll
    for (int o = 16; o > 0; o >>= 1) {
        float m2 = __shfl_xor_sync(0xffffffff, bm, o);
        int   p2 = __shfl_xor_sync(0xffffffff, bp, o);
        int   a2 = __shfl_xor_sync(0xffffffff, ba, o);
        if (m2 > bm || (m2 == bm && p2 < bp)) { bm = m2; bp = p2; ba = a2; }
    }
    float se = s0 * __expf(m0 - bm);
#pragma unroll
    for (int o = 16; o > 0; o >>= 1) se += __shfl_xor_sync(0xffffffff, se, o);

    // col partials
    float cm0 = g_cpm[lane * NTOT + i];
    float cs0 = g_cps[lane * NTOT + i];
    float cm = cm0;
#pragma unroll
    for (int o = 16; o > 0; o >>= 1) cm = fmaxf(cm, __shfl_xor_sync(0xffffffff, cm, o));
    float cse = cs0 * __expf(cm0 - cm);
#pragma unroll
    for (int o = 16; o > 0; o >>= 1) cse += __shfl_xor_sync(0xffffffff, cse, o);

    // triplet
    const float* a  = A + (size_t)i * DIM;
    const float* bpos = B + (size_t)i * DIM;
    const float* bneg = B + (size_t)g_hard[i] * DIM;
    float ps = 0.f, ns = 0.f;
#pragma unroll
    for (int t = lane; t < DIM; t += 32) {
        float av = a[t];
        float d1 = av - bpos[t] + 1e-6f; ps += d1 * d1;
        float d2 = av - bneg[t] + 1e-6f; ns += d2 * d2;
    }
#pragma unroll
    for (int o = 16; o > 0; o >>= 1) {
        ps += __shfl_xor_sync(0xffffffff, ps, o);
        ns += __shfl_xor_sync(0xffffffff, ns, o);
    }

    if (lane == 0) {
        float d = g_diag[i];
        float trip = sqrtf(ps) - sqrtf(ns) + 0.5f;
        g_terms[i]            = bm + logf(se) - d;
        g_terms[NTOT + i]     = cm + logf(cse) - d;
        g_terms[2 * NTOT + i] = trip > 0.f ? trip : 0.f;
        g_terms[3 * NTOT + i] = (ba == i) ? 1.0f : 0.0f;
    }
}

// ---------------- final deterministic reduction ----------------
__global__ void final_reduce(float* __restrict__ out) {
    __shared__ float sm[256];
    int tid = threadIdx.x;
    float sums[4];
    for (int cc = 0; cc < 4; cc++) {
        float s = 0.f;
        for (int j = tid; j < NTOT; j += 256) s += g_terms[cc * NTOT + j];
        sm[tid] = s;
        __syncthreads();
        for (int st = 128; st > 0; st >>= 1) {
            if (tid < st) sm[tid] += sm[tid + st];
            __syncthreads();
        }
        sums[cc] = sm[0];
        __syncthreads();
    }
    if (tid == 0) {
        float info = 0.5f * (sums[0] + sums[1]) / (float)NTOT;
        float trip = sums[2] / (float)NTOT;
        float acc  = sums[3] / (float)NTOT;
        out[0] = info + 0.1f * trip;
        out[1] = info;
        out[2] = trip;
        out[3] = acc;
    }
}

extern "C" void kernel_launch(void* const* d_in, const int* in_sizes, int n_in,
                              void* d_out, int out_size) {
    const float* A = (const float*)d_in[0];
    const float* B = (const float*)d_in[1];
    float* out = (float*)d_out;

    static bool configured = false;
    if (!configured) {
        cudaFuncSetAttribute(gemm_fused, cudaFuncAttributeMaxDynamicSharedMemorySize,
                             SMEM_GEMM);
        configured = true;
    }

    split_f16<<<512, 256>>>(A, B);
    gemm_fused<<<dim3(32, 32), 256, SMEM_GEMM>>>();
    merge_all<<<512, 256>>>(A, B);
    final_reduce<<<1, 256>>>(out);
}